// round 12
// baseline (speedup 1.0000x reference)
#include <cuda_runtime.h>
#include <cuda_fp16.h>
#include <math.h>
#include <stdint.h>

// Problem constants
#define BT_  16384   // B*T
#define F_   64
#define E_   64
#define H_   8
#define P_   512
#define K_   1024    // 2*F*H

// GEMM tiling: fine tiles for wave balance. CTA 64x128, BK=64, 16 k-steps.
// t = 256 m-tiles x 4 n-tiles = 1024 CTAs -> ceil(1024/148)=7 per SM (1.2% waste)
#define BM 64
#define BN 128
#define BK 64
#define NT (K_ / BK)     // 16
#define ROWB 144         // 128B payload + 16B pad (conflict-free ldmatrix)
#define A_BYTES (BM * ROWB)            // 9216
#define B_BYTES (BN * ROWB)            // 18432
#define STAGE_B (A_BYTES + B_BYTES)    // 27648
#define NSTAGE 3
#define SMEM_BYTES (NSTAGE * STAGE_B)  // 82944  (occ 2)

// Scratch (static device globals)
__device__ __half g_Wt[P_ * K_];      // folded weights [P][K] fp16 (1MB)
__device__ __half g_Hbuf[BT_ * K_];   // tanh activations [BT][K] fp16 (32MB, L2-resident)
__device__ float  g_bias[P_];

// ---------------------------------------------------------------------------
// helpers
// ---------------------------------------------------------------------------
__device__ __forceinline__ uint32_t smem_u32(const void* p) {
    uint32_t a;
    asm("{ .reg .u64 t; cvta.to.shared.u64 t, %1; cvt.u32.u64 %0, t; }" : "=r"(a) : "l"(p));
    return a;
}

__device__ __forceinline__ void cp16(uint32_t dst, const void* src) {
    asm volatile("cp.async.cg.shared.global [%0], [%1], 16;" :: "r"(dst), "l"(src) : "memory");
}

#define CP_COMMIT()  asm volatile("cp.async.commit_group;" ::: "memory")
#define CP_WAIT(n)   asm volatile("cp.async.wait_group %0;" :: "n"(n) : "memory")

__device__ __forceinline__ void ldmx4(uint32_t r[4], uint32_t addr) {
    asm volatile("ldmatrix.sync.aligned.m8n8.x4.shared.b16 {%0,%1,%2,%3}, [%4];"
                 : "=r"(r[0]), "=r"(r[1]), "=r"(r[2]), "=r"(r[3]) : "r"(addr));
}

__device__ __forceinline__ void mma_f16(float c[4], const uint32_t a[4],
                                        const uint32_t b0, const uint32_t b1) {
    asm volatile(
        "mma.sync.aligned.m16n8k16.row.col.f32.f16.f16.f32 "
        "{%0,%1,%2,%3}, {%4,%5,%6,%7}, {%8,%9}, {%0,%1,%2,%3};"
        : "+f"(c[0]), "+f"(c[1]), "+f"(c[2]), "+f"(c[3])
        : "r"(a[0]), "r"(a[1]), "r"(a[2]), "r"(a[3]), "r"(b0), "r"(b1));
}

__device__ __forceinline__ float tanh_fast(float x) {
    float r;
    asm("tanh.approx.f32 %0, %1;" : "=f"(r) : "f"(x));
    return r;
}

__device__ __forceinline__ uint32_t pack_half2(float lo, float hi) {
    uint32_t r;
    asm("cvt.rn.f16x2.f32 %0, %1, %2;" : "=r"(r) : "f"(hi), "f"(lo));
    return r;
}

// ---------------------------------------------------------------------------
// Prep kernel (128 threads/block):
//   blocks [0,128): W-fold -> g_Wt fp16 (block=(f,branch), thread: 4 p via f4)
//   blocks [128, 128+16384): tanh -> g_Hbuf fp16 (thread: one (bt,branch,f) row)
// ---------------------------------------------------------------------------
__global__ void __launch_bounds__(128) prep(
        const float* __restrict__ x,   const float* __restrict__ tm,
        const float* __restrict__ w1v, const float* __restrict__ b1v,
        const float* __restrict__ w2v,
        const float* __restrict__ w1t, const float* __restrict__ b1t,
        const float* __restrict__ w2t,
        const float* __restrict__ wx,  const float* __restrict__ bx,
        const float* __restrict__ wt,  const float* __restrict__ bt) {
    const int bid = blockIdx.x;
    const int t   = threadIdx.x;

    if (bid < 128) {
        // ---- W-fold ----
        const int f      = bid >> 1;
        const int branch = bid & 1;
        const float* __restrict__ w2 = branch ? w2t : w2v;
        const float* __restrict__ wp = branch ? wt  : wx;

        __shared__ float s_w2[H_ * E_];
#pragma unroll
        for (int i = 0; i < 4; i++)
            s_w2[t + i * 128] = w2[f * H_ * E_ + t + i * 128];
        __syncthreads();

        const int p4 = t * 4;   // 4 consecutive p per thread
        float acc[H_][4];
#pragma unroll
        for (int h = 0; h < H_; h++)
#pragma unroll
            for (int j = 0; j < 4; j++) acc[h][j] = 0.f;

#pragma unroll 8
        for (int e = 0; e < E_; e++) {
            const float4 w = *(const float4*)&wp[(size_t)(f * E_ + e) * P_ + p4];
#pragma unroll
            for (int h = 0; h < H_; h++) {
                const float s = s_w2[h * E_ + e];
                acc[h][0] = fmaf(s, w.x, acc[h][0]);
                acc[h][1] = fmaf(s, w.y, acc[h][1]);
                acc[h][2] = fmaf(s, w.z, acc[h][2]);
                acc[h][3] = fmaf(s, w.w, acc[h][3]);
            }
        }
        const size_t koff = branch * 512 + f * H_;
#pragma unroll
        for (int j = 0; j < 4; j++) {
            uint4 st;
            st.x = pack_half2(acc[0][j], acc[1][j]);
            st.y = pack_half2(acc[2][j], acc[3][j]);
            st.z = pack_half2(acc[4][j], acc[5][j]);
            st.w = pack_half2(acc[6][j], acc[7][j]);
            *(uint4*)&g_Wt[(size_t)(p4 + j) * K_ + koff] = st;
        }
        if (bid == 0) {
#pragma unroll
            for (int i = 0; i < 4; i++)
                g_bias[t + i * 128] = bx[t + i * 128] + bt[t + i * 128];
        }
    } else {
        // ---- tanh activations ----
        const int idx    = (bid - 128) * 128 + t;    // [0, BT*128)
        const int bt_    = idx >> 7;
        const int r      = idx & 127;
        const int branch = r >> 6;
        const int f      = r & 63;

        const float inp = (branch ? tm : x)[bt_ * F_ + f];
        const float4 w0 = *(const float4*)&(branch ? w1t : w1v)[f * H_];
        const float4 w1 = *(const float4*)&(branch ? w1t : w1v)[f * H_ + 4];
        const float4 c0 = *(const float4*)&(branch ? b1t : b1v)[f * H_];
        const float4 c1 = *(const float4*)&(branch ? b1t : b1v)[f * H_ + 4];

        uint4 st;
        st.x = pack_half2(tanh_fast(fmaf(inp, w0.x, c0.x)), tanh_fast(fmaf(inp, w0.y, c0.y)));
        st.y = pack_half2(tanh_fast(fmaf(inp, w0.z, c0.z)), tanh_fast(fmaf(inp, w0.w, c0.w)));
        st.z = pack_half2(tanh_fast(fmaf(inp, w1.x, c1.x)), tanh_fast(fmaf(inp, w1.y, c1.y)));
        st.w = pack_half2(tanh_fast(fmaf(inp, w1.z, c1.z)), tanh_fast(fmaf(inp, w1.w, c1.w)));
        *(uint4*)&g_Hbuf[(size_t)bt_ * K_ + branch * 512 + f * H_] = st;
    }
}

// ---------------------------------------------------------------------------
// GEMM: C[16384,512] = Hbuf @ Wt^T + bias
// CTA 64x128, 256 threads (8 warps: 2m x 4n), warp 32x32, 3-stage, occ 2
// grid (512/BN=4, 16384/BM=256) = 1024 CTAs
// ---------------------------------------------------------------------------
__device__ __forceinline__ void fill_stage(uint32_t sbase, int stage, int kt,
                                           int bm, int bn, int tid) {
    const uint32_t a0 = sbase + (uint32_t)(stage * STAGE_B);
    const uint32_t b0 = a0 + (uint32_t)A_BYTES;
    const int k0 = kt * BK;
    // A: 64 rows x 8 chunks = 512 chunks; 2 per thread
#pragma unroll
    for (int i = 0; i < 2; i++) {
        const int c   = tid + i * 256;
        const int row = c >> 3;
        const int ch  = c & 7;
        cp16(a0 + (uint32_t)(row * ROWB + ch * 16),
             g_Hbuf + (size_t)(bm + row) * K_ + k0 + ch * 8);
    }
    // B: 128 rows x 8 chunks = 1024 chunks; 4 per thread
#pragma unroll
    for (int i = 0; i < 4; i++) {
        const int c   = tid + i * 256;
        const int row = c >> 3;
        const int ch  = c & 7;
        cp16(b0 + (uint32_t)(row * ROWB + ch * 16),
             g_Wt + (size_t)(bn + row) * K_ + k0 + ch * 8);
    }
}

__global__ void __launch_bounds__(256, 2) gemm_mma(float* __restrict__ C) {
    extern __shared__ char sm[];
    const uint32_t sbase = smem_u32(sm);
    const int tid  = threadIdx.x;
    const int lane = tid & 31;
    const int wid  = tid >> 5;
    const int wm   = (wid & 1) * 32;       // 2 warps in M
    const int wn   = (wid >> 1) * 32;      // 4 warps in N
    const int bm   = blockIdx.y * BM;
    const int bn   = blockIdx.x * BN;

    // ldmatrix lane addresses (bytes within tile)
    const uint32_t a_lane = (uint32_t)((wm + (lane & 15)) * ROWB + ((lane >> 4) & 1) * 16);
    const uint32_t b_lane = (uint32_t)((wn + (lane & 7) + ((lane >> 4) & 1) * 8) * ROWB
                                       + ((lane >> 3) & 1) * 16);

    float acc[2][4][4];
#pragma unroll
    for (int mt = 0; mt < 2; mt++)
#pragma unroll
        for (int nt = 0; nt < 4; nt++)
#pragma unroll
            for (int i = 0; i < 4; i++) acc[mt][nt][i] = 0.f;

    fill_stage(sbase, 0, 0, bm, bn, tid); CP_COMMIT();
    fill_stage(sbase, 1, 1, bm, bn, tid); CP_COMMIT();

    for (int kt = 0; kt < NT; kt++) {
        const int stage = kt % 3;
        CP_WAIT(1);
        __syncthreads();

        if (kt + 2 < NT) {
            int ns = stage + 2; if (ns >= 3) ns -= 3;
            fill_stage(sbase, ns, kt + 2, bm, bn, tid);
        }
        CP_COMMIT();    // one commit per iter keeps wait_group arithmetic exact

        const uint32_t Abase = sbase + (uint32_t)(stage * STAGE_B);
        const uint32_t Bbase = Abase + (uint32_t)A_BYTES;

        uint32_t a[2][8];    // per ks: 2 mt x 4 regs, double-buffered
        uint32_t b[2][8];    // per ks: 2 ldmx4 -> 4 nt x 2 regs

        // preload ks=0
        ldmx4(&a[0][0], Abase + a_lane);
        ldmx4(&a[0][4], Abase + a_lane + (uint32_t)(16 * ROWB));
        ldmx4(&b[0][0], Bbase + b_lane);
        ldmx4(&b[0][4], Bbase + b_lane + (uint32_t)(16 * ROWB));

#pragma unroll
        for (int ks = 0; ks < 4; ks++) {
            const uint32_t* ac = a[ks & 1];
            const uint32_t* bc = b[ks & 1];
            if (ks < 3) {    // prefetch ks+1
                uint32_t* an = a[(ks + 1) & 1];
                uint32_t* bnx = b[(ks + 1) & 1];
                ldmx4(&an[0], Abase + a_lane + (uint32_t)((ks + 1) * 32));
                ldmx4(&an[4], Abase + a_lane + (uint32_t)(16 * ROWB + (ks + 1) * 32));
                ldmx4(&bnx[0], Bbase + b_lane + (uint32_t)((ks + 1) * 32));
                ldmx4(&bnx[4], Bbase + b_lane + (uint32_t)(16 * ROWB + (ks + 1) * 32));
            }
#pragma unroll
            for (int mt = 0; mt < 2; mt++)
#pragma unroll
                for (int nt = 0; nt < 4; nt++)
                    mma_f16(acc[mt][nt], &ac[mt * 4], bc[nt * 2], bc[nt * 2 + 1]);
        }
    }

    // Epilogue: thread owns rows {g, g+8}, cols {qc, qc+1} per (mt, nt) tile
    const int g  = lane >> 2;
    const int qc = (lane & 3) * 2;
#pragma unroll
    for (int nt = 0; nt < 4; nt++) {
        const int col = bn + wn + nt * 8 + qc;
        const float2 bias = *(const float2*)&g_bias[col];
#pragma unroll
        for (int mt = 0; mt < 2; mt++) {
            const int row = bm + wm + mt * 16 + g;
            float2 v0, v1;
            v0.x = acc[mt][nt][0] + bias.x;
            v0.y = acc[mt][nt][1] + bias.y;
            v1.x = acc[mt][nt][2] + bias.x;
            v1.y = acc[mt][nt][3] + bias.y;
            *(float2*)&C[(size_t)row * P_ + col]       = v0;
            *(float2*)&C[(size_t)(row + 8) * P_ + col] = v1;
        }
    }
}

// ---------------------------------------------------------------------------
// Launch: x, time, w1v, b1v, w2v, w1t, b1t, w2t, wx, bx, wt, bt
// ---------------------------------------------------------------------------
extern "C" void kernel_launch(void* const* d_in, const int* in_sizes, int n_in,
                              void* d_out, int out_size) {
    const float* x    = (const float*)d_in[0];
    const float* tmi  = (const float*)d_in[1];
    const float* w1v  = (const float*)d_in[2];
    const float* b1v  = (const float*)d_in[3];
    const float* w2v  = (const float*)d_in[4];
    const float* w1t  = (const float*)d_in[5];
    const float* b1t  = (const float*)d_in[6];
    const float* w2t  = (const float*)d_in[7];
    const float* wx   = (const float*)d_in[8];
    const float* bx   = (const float*)d_in[9];
    const float* wt   = (const float*)d_in[10];
    const float* bt   = (const float*)d_in[11];
    float* out = (float*)d_out;

    static bool attr_set = false;
    if (!attr_set) {
        cudaFuncSetAttribute(gemm_mma, cudaFuncAttributeMaxDynamicSharedMemorySize, SMEM_BYTES);
        attr_set = true;
    }

    prep<<<128 + (BT_ * 128) / 128, 128>>>(x, tmi, w1v, b1v, w2v, w1t, b1t, w2t, wx, bx, wt, bt);
    gemm_mma<<<dim3(P_ / BN, BT_ / BM), 256, SMEM_BYTES>>>(out);
}